// round 17
// baseline (speedup 1.0000x reference)
#include <cuda_runtime.h>
#include <cuda_fp16.h>
#include <cstdint>

#define N_ 2
#define C_ 64
#define D_ 8
#define H_ 56
#define W_ 56
#define G_ 8
#define K_ 27
#define CO_OFF 648
#define P_ (D_*H_*W_)          // 25088 = 112 * 224
#define DP_ (D_+2)
#define HP_ (H_+2)
#define WP_ (W_+2)
#define PPAD_ (DP_*HP_*WP_)    // 33640
#define HPWP_ (HP_*WP_)
#define KTOT 1728              // 64*27 == 8*27*8
#define P8_ (P_/8)             // 3136

#define PREP_W0H (768*KTOT)    // fp16 w_off (648 real, pad 768 for BM=128)
#define PREP_W1H (64*KTOT)
#define PREP_W2H (64*KTOT)

// ---------------- scratch (no allocation allowed) ----------------
__device__ float  g_xpad[N_*C_*PPAD_];     // padded input
__device__ float  g_y2pad[N_*C_*PPAD_];    // padded bn1+relu output
__device__ float  g_off[N_*CO_OFF*P_];     // offset tensor (130 MB)
__device__ float4 g_xt[N_*G_*P_*2];        // x transposed [n][g][p][8ch]
__device__ __half g_valsh[(size_t)N_*KTOT*P_]; // sampled values fp16 (173 MB)
__device__ float  g_y1[N_*C_*P_];          // deform conv output
__device__ float  g_y3[N_*C_*P_];          // conv2 output
__device__ float  g_stats[4*C_];           // mean1, istd1, mean2, istd2
__device__ __half g_woffh[PREP_W0H];       // fp16 w_off [cog 768][k 1728]
__device__ __half g_w1h[PREP_W1H];         // fp16 w1 [o][1728]
__device__ __half g_w2h[PREP_W2H];         // fp16 w2 [o][1728]
__device__ __half g_xc[(size_t)N_*KTOT*P_]; // im2col fp16 [n][k][p] (reused)

// ---------------- helpers ----------------
__device__ __forceinline__ void mma_fp16(float c[4], const uint32_t a[4],
                                         uint32_t b0, uint32_t b1) {
    asm volatile(
        "mma.sync.aligned.m16n8k16.row.col.f32.f16.f16.f32 "
        "{%0,%1,%2,%3}, {%4,%5,%6,%7}, {%8,%9}, {%0,%1,%2,%3};"
        : "+f"(c[0]), "+f"(c[1]), "+f"(c[2]), "+f"(c[3])
        : "r"(a[0]), "r"(a[1]), "r"(a[2]), "r"(a[3]), "r"(b0), "r"(b1));
}

// ---------------- kernel P: weight prep (all fp16, dense k layouts) ----------------
__global__ void prep_kernel(const float* __restrict__ w_off,
                            const float* __restrict__ w1,
                            const float* __restrict__ w2) {
    int idx = blockIdx.x * 256 + threadIdx.x;
    if (idx < PREP_W0H) {
        int k = idx % KTOT, cog = idx / KTOT;
        float v = (cog < CO_OFF) ? w_off[(size_t)cog * KTOT + k] : 0.f;
        g_woffh[idx] = __float2half_rn(v);
    } else if (idx < PREP_W0H + PREP_W1H) {
        int r = idx - PREP_W0H;
        int kd = r % KTOT, o = r / KTOT;
        int cl = kd & 7, gk = kd >> 3;
        int g = gk / 27, k = gk - g * 27;
        g_w1h[r] = __float2half_rn(w1[(o * C_ + g * 8 + cl) * K_ + k]);
    } else if (idx < PREP_W0H + PREP_W1H + PREP_W2H) {
        int r = idx - PREP_W0H - PREP_W1H;
        g_w2h[r] = __float2half_rn(w2[r]);
    }
}

// ---------------- kernel T: transpose x -> [n][g][p][8ch] ----------------
__global__ void transpose_kernel(const float* __restrict__ x) {
    int idx = blockIdx.x * 256 + threadIdx.x;
    if (idx >= N_*G_*P_) return;
    int p = idx % P_;
    int g = (idx / P_) % G_;
    int n = idx / (P_ * G_);
    const float* xs = x + ((size_t)(n * C_ + g * 8)) * P_ + p;
    float4 a, b;
    a.x = xs[0];            a.y = xs[(size_t)P_];
    a.z = xs[2*(size_t)P_]; a.w = xs[3*(size_t)P_];
    b.x = xs[4*(size_t)P_]; b.y = xs[5*(size_t)P_];
    b.z = xs[6*(size_t)P_]; b.w = xs[7*(size_t)P_];
    g_xt[(size_t)idx * 2]     = a;
    g_xt[(size_t)idx * 2 + 1] = b;
}

// ---------------- kernel 0: build padded x ----------------
__global__ void padinit_kernel(const float* __restrict__ x) {
    int idx = blockIdx.x * 256 + threadIdx.x;
    if (idx >= N_*C_*PPAD_) return;
    int wp = idx % WP_;
    int hp = (idx / WP_) % HP_;
    int dp = (idx / (WP_*HP_)) % DP_;
    int nc = idx / PPAD_;
    bool interior = (dp >= 1 && dp <= D_ && hp >= 1 && hp <= H_ && wp >= 1 && wp <= W_);
    float v = 0.f;
    if (interior)
        v = x[nc * P_ + (dp-1) * (H_*W_) + (hp-1) * W_ + (wp-1)];
    g_xpad[idx] = v;
    if (!interior) g_y2pad[idx] = 0.f;
}

// ---------------- kernel I: im2col fp16  g_xc[n][k][p] ----------------
// grid: (13, KTOT, N_), block 256 — k/n uniform per block (cheap ALU)
__global__ void im2col_kernel(int use_y2) {
    int p8 = blockIdx.x * 256 + threadIdx.x;
    if (p8 >= P8_) return;
    int k = blockIdx.y;
    int n = blockIdx.z;
    int ci = k / 27, tap = k - ci * 27;
    int kd = tap / 9, kh = (tap / 3) % 3, kw = tap % 3;
    int w8 = (p8 % 7) * 8;
    int h  = (p8 / 7) % H_;
    int d  = p8 / 392;
    const float* base = use_y2 ? g_y2pad : g_xpad;
    const float* src = base + (size_t)(n * C_ + ci) * PPAD_
                       + (d + kd) * HPWP_ + (h + kh) * WP_ + (w8 + kw);
    __half out[8];
#pragma unroll
    for (int j = 0; j < 8; j++) out[j] = __float2half_rn(src[j]);
    *(uint4*)(g_xc + ((size_t)(n * KTOT + k)) * P_ + p8 * 8) = *(const uint4*)out;
}

// ---------------- BM=64 fp16 GEMM (for co_tot=64 cases) ----------------
__global__ __launch_bounds__(128) void gemm_fp16_kernel(
    const __half* __restrict__ A, const __half* __restrict__ Bm,
    float* __restrict__ outb, const float* __restrict__ bias, int co_tot) {
    __shared__ uint32_t Wsu[64*36];
    __shared__ uint32_t Bsu[2][32*120];

    int cot = blockIdx.x;
    int bx  = blockIdx.y;
    int pt  = bx % 112;
    int n   = bx / 112;
    int pbase = pt * 224;

    int tid  = threadIdx.x;
    int lane = tid & 31, warp = tid >> 5;
    int gid  = lane >> 2, tg = lane & 3;
    int nw   = warp;
    int hb   = nw >> 1, nsub = nw & 1;

    float c[4][7][4];
#pragma unroll
    for (int mt = 0; mt < 4; mt++)
#pragma unroll
        for (int nt = 0; nt < 7; nt++)
#pragma unroll
            for (int i = 0; i < 4; i++) c[mt][nt][i] = 0.f;

    for (int kc = 0; kc < 27; kc++) {
        int k0 = kc * 64;
        __syncthreads();
#pragma unroll
        for (int i = tid; i < 512; i += 128) {
            int co = i >> 3, f = i & 7;
            uint4 v = *(const uint4*)(A + ((size_t)(cot * 64 + co)) * KTOT + k0 + f * 8);
            *(uint4*)&Wsu[co * 36 + f * 4] = v;
        }
#pragma unroll
        for (int i = tid; i < 896; i += 128) {
            int hb2 = i / 448;
            int r   = i - hb2 * 448;
            int kp  = r / 14, pg = r - kp * 14;
            int pos0 = pg * 8;
            const __half* r0 = Bm + ((size_t)(n * KTOT + k0 + 2 * kp)) * P_
                               + pbase + hb2 * 112 + pos0;
            uint4 a = *(const uint4*)r0;
            uint4 b = *(const uint4*)(r0 + P_);
            uint32_t o0 = __byte_perm(a.x, b.x, 0x5410), o1 = __byte_perm(a.x, b.x, 0x7632);
            uint32_t o2 = __byte_perm(a.y, b.y, 0x5410), o3 = __byte_perm(a.y, b.y, 0x7632);
            uint32_t o4 = __byte_perm(a.z, b.z, 0x5410), o5 = __byte_perm(a.z, b.z, 0x7632);
            uint32_t o6 = __byte_perm(a.w, b.w, 0x5410), o7 = __byte_perm(a.w, b.w, 0x7632);
            int base = kp * 120 + pos0;
            uint4 u0; u0.x = o0; u0.y = o1; u0.z = o2; u0.w = o3;
            uint4 u1; u1.x = o4; u1.y = o5; u1.z = o6; u1.w = o7;
            *(uint4*)&Bsu[hb2][base]     = u0;
            *(uint4*)&Bsu[hb2][base + 4] = u1;
        }
        __syncthreads();

#pragma unroll
        for (int ks = 0; ks < 4; ks++) {
            uint32_t a[4][4];
#pragma unroll
            for (int mt = 0; mt < 4; mt++) {
                int r = mt * 16 + gid;
                a[mt][0] = Wsu[r * 36 + ks * 8 + tg];
                a[mt][1] = Wsu[(r + 8) * 36 + ks * 8 + tg];
                a[mt][2] = Wsu[r * 36 + ks * 8 + tg + 4];
                a[mt][3] = Wsu[(r + 8) * 36 + ks * 8 + tg + 4];
            }
#pragma unroll
            for (int nt = 0; nt < 7; nt++) {
                int col = nsub * 56 + nt * 8 + gid;
                uint32_t b0 = Bsu[hb][(ks * 8 + tg) * 120 + col];
                uint32_t b1 = Bsu[hb][(ks * 8 + tg + 4) * 120 + col];
#pragma unroll
                for (int mt = 0; mt < 4; mt++)
                    mma_fp16(c[mt][nt], a[mt], b0, b1);
            }
        }
    }

#pragma unroll
    for (int mt = 0; mt < 4; mt++) {
#pragma unroll
        for (int half = 0; half < 2; half++) {
            int co = cot * 64 + mt * 16 + gid + half * 8;
            if (co < co_tot) {
                float bo = bias ? bias[co] : 0.f;
                float* outp = outb + ((size_t)(n * co_tot + co)) * P_ + pbase;
#pragma unroll
                for (int nt = 0; nt < 7; nt++) {
                    int w0 = nw * 56 + nt * 8 + tg * 2;
                    float2 st;
                    st.x = c[mt][nt][half * 2 + 0] + bo;
                    st.y = c[mt][nt][half * 2 + 1] + bo;
                    *(float2*)&outp[w0] = st;
                }
            }
        }
    }
}

// ---------------- BM=128 fp16 GEMM (offconv) ----------------
// BM=128, BN=224, 256 thr: 8 warps = 2M x 4N, each warp M=64 x N=56.
// grid: (6, 224) — co fastest (L2 B-sharing)
__global__ __launch_bounds__(256) void gemm_fp16_bm128_kernel(
    const __half* __restrict__ A, const __half* __restrict__ Bm,
    float* __restrict__ outb, const float* __restrict__ bias, int co_tot) {
    __shared__ uint32_t Wsu[128*36];      // 18 KB
    __shared__ uint32_t Bsu[2][32*120];   // 30 KB

    int cot = blockIdx.x;
    int bx  = blockIdx.y;
    int pt  = bx % 112;
    int n   = bx / 112;
    int pbase = pt * 224;

    int tid  = threadIdx.x;
    int lane = tid & 31, warp = tid >> 5;
    int gid  = lane >> 2, tg = lane & 3;
    int mw   = warp >> 2, nw = warp & 3;
    int hb   = nw >> 1, nsub = nw & 1;

    float c[4][7][4];
#pragma unroll
    for (int mt = 0; mt < 4; mt++)
#pragma unroll
        for (int nt = 0; nt < 7; nt++)
#pragma unroll
            for (int i = 0; i < 4; i++) c[mt][nt][i] = 0.f;

    for (int kc = 0; kc < 27; kc++) {
        int k0 = kc * 64;
        __syncthreads();
        // stage A: 1024 uint4 (128 co x 8 f), 4 per thread
#pragma unroll
        for (int i = tid; i < 1024; i += 256) {
            int co = i >> 3, f = i & 7;
            uint4 v = *(const uint4*)(A + ((size_t)(cot * 128 + co)) * KTOT + k0 + f * 8);
            *(uint4*)&Wsu[co * 36 + f * 4] = v;
        }
        // stage B: 896 items
#pragma unroll
        for (int i = tid; i < 896; i += 256) {
            int hb2 = i / 448;
            int r   = i - hb2 * 448;
            int kp  = r / 14, pg = r - kp * 14;
            int pos0 = pg * 8;
            const __half* r0 = Bm + ((size_t)(n * KTOT + k0 + 2 * kp)) * P_
                               + pbase + hb2 * 112 + pos0;
            uint4 a = *(const uint4*)r0;
            uint4 b = *(const uint4*)(r0 + P_);
            uint32_t o0 = __byte_perm(a.x, b.x, 0x5410), o1 = __byte_perm(a.x, b.x, 0x7632);
            uint32_t o2 = __byte_perm(a.y, b.y, 0x5410), o3 = __byte_perm(a.y, b.y, 0x7632);
            uint32_t o4 = __byte_perm(a.z, b.z, 0x5410), o5 = __byte_perm(a.z, b.z, 0x7632);
            uint32_t o6 = __byte_perm(a.w, b.w, 0x5410), o7 = __byte_perm(a.w, b.w, 0x7632);
            int base = kp * 120 + pos0;
            uint4 u0; u0.x = o0; u0.y = o1; u0.z = o2; u0.w = o3;
            uint4 u1; u1.x = o4; u1.y = o5; u1.z = o6; u1.w = o7;
            *(uint4*)&Bsu[hb2][base]     = u0;
            *(uint4*)&Bsu[hb2][base + 4] = u1;
        }
        __syncthreads();

#pragma unroll
        for (int ks = 0; ks < 4; ks++) {
            uint32_t a[4][4];
#pragma unroll
            for (int mt = 0; mt < 4; mt++) {
                int r = mw * 64 + mt * 16 + gid;
                a[mt][0] = Wsu[r * 36 + ks * 8 + tg];
                a[mt][1] = Wsu[(r + 8) * 36 + ks * 8 + tg];
                a[mt][2] = Wsu[r * 36 + ks * 8 + tg + 4];
                a[mt][3] = Wsu[(r + 8) * 36 + ks * 8 + tg + 4];
            }
#pragma unroll
            for (int nt = 0; nt < 7; nt++) {
                int col = nsub * 56 + nt * 8 + gid;
                uint32_t b0 = Bsu[hb][(ks * 8 + tg) * 120 + col];
                uint32_t b1 = Bsu[hb][(ks * 8 + tg + 4) * 120 + col];
#pragma unroll
                for (int mt = 0; mt < 4; mt++)
                    mma_fp16(c[mt][nt], a[mt], b0, b1);
            }
        }
    }

#pragma unroll
    for (int mt = 0; mt < 4; mt++) {
#pragma unroll
        for (int half = 0; half < 2; half++) {
            int co = cot * 128 + mw * 64 + mt * 16 + gid + half * 8;
            if (co < co_tot) {
                float bo = bias ? bias[co] : 0.f;
                float* outp = outb + ((size_t)(n * co_tot + co)) * P_ + pbase;
#pragma unroll
                for (int nt = 0; nt < 7; nt++) {
                    int w0 = nw * 56 + nt * 8 + tg * 2;
                    float2 st;
                    st.x = c[mt][nt][half * 2 + 0] + bo;
                    st.y = c[mt][nt][half * 2 + 1] + bo;
                    *(float2*)&outp[w0] = st;
                }
            }
        }
    }
}

// ---------------- kernel 2a: deform gather (float4 in, fp16 out) ----
// grid: (98, G*K, N) — g,k,n uniform per block
__global__ __launch_bounds__(256) void deform_gather_kernel() {
    int p = blockIdx.x * 256 + threadIdx.x;
    int gk = blockIdx.y;
    int k = gk % K_;
    int g = gk / K_;
    int n = blockIdx.z;

    int w = p % W_;
    int h = (p / W_) % H_;
    int d = p / (W_ * H_);

    int kd = k / 9, kh = (k / 3) % 3, kw = k % 3;
    size_t obase = ((size_t)(n * CO_OFF + (g*K_ + k) * 3)) * P_ + p;
    float od = __ldg(&g_off[obase]);
    float oh = __ldg(&g_off[obase + P_]);
    float ow = __ldg(&g_off[obase + 2*(size_t)P_]);

    float pd = (float)(d + kd - 1) + od;
    float ph = (float)(h + kh - 1) + oh;
    float pw = (float)(w + kw - 1) + ow;
    float d0f = floorf(pd), h0f = floorf(ph), w0f = floorf(pw);
    float fd = pd - d0f, fh = ph - h0f, fw = pw - w0f;
    int d0 = (int)d0f, h0 = (int)h0f, w0 = (int)w0f;

    const float4* xg = (const float4*)g_xt + ((size_t)(n * G_ + g)) * P_ * 2;

    float s0=0.f,s1=0.f,s2=0.f,s3=0.f,s4=0.f,s5=0.f,s6=0.f,s7=0.f;
#pragma unroll
    for (int c8 = 0; c8 < 8; c8++) {
        int cd = c8 >> 2, ch = (c8 >> 1) & 1, cw = c8 & 1;
        int id = d0 + cd, ih = h0 + ch, iw = w0 + cw;
        float wt = (cd ? fd : 1.f - fd) * (ch ? fh : 1.f - fh) * (cw ? fw : 1.f - fw);
        bool valid = (id >= 0 && id < D_ && ih >= 0 && ih < H_ && iw >= 0 && iw < W_);
        int idc = min(max(id, 0), D_-1);
        int ihc = min(max(ih, 0), H_-1);
        int iwc = min(max(iw, 0), W_-1);
        int lin = (idc * H_ + ihc) * W_ + iwc;
        wt = valid ? wt : 0.f;
        float4 va = __ldg(&xg[(size_t)lin * 2]);
        float4 vb = __ldg(&xg[(size_t)lin * 2 + 1]);
        s0 += va.x * wt; s1 += va.y * wt; s2 += va.z * wt; s3 += va.w * wt;
        s4 += vb.x * wt; s5 += vb.y * wt; s6 += vb.z * wt; s7 += vb.w * wt;
    }

    __half* vout = g_valsh + ((size_t)(n * KTOT + (g * K_ + k) * 8)) * P_ + p;
    vout[0]            = __float2half_rn(s0);
    vout[(size_t)P_]   = __float2half_rn(s1);
    vout[2*(size_t)P_] = __float2half_rn(s2);
    vout[3*(size_t)P_] = __float2half_rn(s3);
    vout[4*(size_t)P_] = __float2half_rn(s4);
    vout[5*(size_t)P_] = __float2half_rn(s5);
    vout[6*(size_t)P_] = __float2half_rn(s6);
    vout[7*(size_t)P_] = __float2half_rn(s7);
}

// ---------------- BN statistics ----------------
__global__ void bnstats_kernel(int which) {
    const float* y = which ? g_y3 : g_y1;
    int c = blockIdx.x;
    int tid = threadIdx.x;
    float s = 0.f, s2 = 0.f;
    for (int n = 0; n < N_; n++) {
        const float* p = y + (n * C_ + c) * P_;
        for (int i = tid; i < P_ / 4; i += 256) {
            float4 v = *(const float4*)&p[i * 4];
            s += v.x + v.y + v.z + v.w;
            s2 += v.x*v.x + v.y*v.y + v.z*v.z + v.w*v.w;
        }
    }
    __shared__ float rs[256], rq[256];
    rs[tid] = s; rq[tid] = s2;
    __syncthreads();
    for (int st = 128; st > 0; st >>= 1) {
        if (tid < st) { rs[tid] += rs[tid+st]; rq[tid] += rq[tid+st]; }
        __syncthreads();
    }
    if (tid == 0) {
        float cnt = (float)(N_ * P_);
        float m = rs[0] / cnt;
        float var = rq[0] / cnt - m * m;
        g_stats[which*128 + c]      = m;
        g_stats[which*128 + 64 + c] = rsqrtf(var + 1e-5f);
    }
}

// ---------------- BN1 apply + relu -> padded buffer ----------------
__global__ void bnrelu_kernel(const float* __restrict__ gamma, const float* __restrict__ beta) {
    int i4 = blockIdx.x * 256 + threadIdx.x;
    if (i4 >= N_*C_*P_/4) return;
    int idx = i4 * 4;
    int c = (idx / P_) % C_;
    float m = g_stats[c], is = g_stats[64 + c];
    float ga = gamma[c], be = beta[c];
    float4 v = *(const float4*)&g_y1[idx];
    v.x = fmaxf((v.x - m) * is * ga + be, 0.f);
    v.y = fmaxf((v.y - m) * is * ga + be, 0.f);
    v.z = fmaxf((v.z - m) * is * ga + be, 0.f);
    v.w = fmaxf((v.w - m) * is * ga + be, 0.f);
    int pp = idx % P_;
    int w = pp % W_, hh = (pp / W_) % H_, dd = pp / (W_*H_);
    int nc = idx / P_;
    float* dst = &g_y2pad[nc * PPAD_ + (dd+1) * HPWP_ + (hh+1) * WP_ + (w+1)];
    dst[0] = v.x; dst[1] = v.y; dst[2] = v.z; dst[3] = v.w;
}

// ---------------- final: bn2 + residual + relu (float4) ----------------
__global__ void final_kernel(const float* __restrict__ x,
                             const float* __restrict__ gamma2,
                             const float* __restrict__ beta2,
                             float* __restrict__ out) {
    int i4 = blockIdx.x * 256 + threadIdx.x;
    if (i4 >= N_*C_*P_/4) return;
    int idx = i4 * 4;
    int c = (idx / P_) % C_;
    float m = g_stats[128 + c], is = g_stats[192 + c];
    float ga = gamma2[c], be = beta2[c];
    float4 v = *(const float4*)&g_y3[idx];
    float4 xr = *(const float4*)&x[idx];
    float4 o;
    o.x = fmaxf((v.x - m) * is * ga + be + xr.x, 0.f);
    o.y = fmaxf((v.y - m) * is * ga + be + xr.y, 0.f);
    o.z = fmaxf((v.z - m) * is * ga + be + xr.z, 0.f);
    o.w = fmaxf((v.w - m) * is * ga + be + xr.w, 0.f);
    *(float4*)&out[idx] = o;
}

// ---------------- launcher ----------------
extern "C" void kernel_launch(void* const* d_in, const int* in_sizes, int n_in,
                              void* d_out, int out_size) {
    const float* x      = (const float*)d_in[0];
    const float* w_off  = (const float*)d_in[1];
    const float* b_off  = (const float*)d_in[2];
    const float* w1     = (const float*)d_in[3];
    const float* gamma1 = (const float*)d_in[4];
    const float* beta1  = (const float*)d_in[5];
    const float* w2     = (const float*)d_in[6];
    const float* b2     = (const float*)d_in[7];
    const float* gamma2 = (const float*)d_in[8];
    const float* beta2  = (const float*)d_in[9];
    float* out = (float*)d_out;

    void *p_woffh, *p_w1h, *p_w2h, *p_xc, *p_valsh, *p_off, *p_y1, *p_y3;
    cudaGetSymbolAddress(&p_woffh, g_woffh);
    cudaGetSymbolAddress(&p_w1h,   g_w1h);
    cudaGetSymbolAddress(&p_w2h,   g_w2h);
    cudaGetSymbolAddress(&p_xc,    g_xc);
    cudaGetSymbolAddress(&p_valsh, g_valsh);
    cudaGetSymbolAddress(&p_off,   g_off);
    cudaGetSymbolAddress(&p_y1,    g_y1);
    cudaGetSymbolAddress(&p_y3,    g_y3);

    int padtot = N_*C_*PPAD_;
    int tot4 = N_*C_*P_/4;
    int preptot = PREP_W0H + PREP_W1H + PREP_W2H;

    prep_kernel<<<(preptot + 255) / 256, 256>>>(w_off, w1, w2);
    padinit_kernel<<<(padtot + 255) / 256, 256>>>(x);
    transpose_kernel<<<(N_*G_*P_ + 255) / 256, 256>>>(x);
    im2col_kernel<<<dim3(13, KTOT, N_), 256>>>(0);
    gemm_fp16_bm128_kernel<<<dim3(6, 224), 256>>>((const __half*)p_woffh, (const __half*)p_xc,
                                                  (float*)p_off, b_off, CO_OFF);
    deform_gather_kernel<<<dim3(98, G_*K_, N_), 256>>>();
    gemm_fp16_kernel<<<dim3(1, 224), 128>>>((const __half*)p_w1h, (const __half*)p_valsh,
                                            (float*)p_y1, (const float*)nullptr, C_);
    bnstats_kernel<<<64, 256>>>(0);
    bnrelu_kernel<<<(tot4 + 255) / 256, 256>>>(gamma1, beta1);
    im2col_kernel<<<dim3(13, KTOT, N_), 256>>>(1);
    gemm_fp16_kernel<<<dim3(1, 224), 128>>>((const __half*)p_w2h, (const __half*)p_xc,
                                            (float*)p_y3, b2, C_);
    bnstats_kernel<<<64, 256>>>(1);
    final_kernel<<<(tot4 + 255) / 256, 256>>>(x, gamma2, beta2, out);
}